// round 5
// baseline (speedup 1.0000x reference)
#include <cuda_runtime.h>
#include <cuda_bf16.h>

#define B_    4
#define SEQ_  4096
#define D_    64
#define V_    512
#define BS_   32
#define R_    128          // SEQ/BS
#define PPB_  8256         // panels per batch = R(R+1)/2
#define CHUNK 32           // max panels per gather CTA (run-aligned)

typedef unsigned long long u64;

// Scratch (device globals — no allocation allowed)
__device__ float g_qT[(size_t)B_ * D_ * SEQ_];            // [b][d][m]
__device__ float g_eT[(size_t)B_ * D_ * V_];              // [b][d][v]
__device__ float g_scores[(size_t)B_ * SEQ_ * V_];        // [b][m][v]
__device__ int   g_ready[B_][32];                         // per (b, m-tile) v-tile count

#define FMA_F32X2(d, a, b, c) \
    asm("fma.rn.f32x2 %0, %1, %2, %3;" : "=l"(d) : "l"(a), "l"(b), "l"(c))
#define PACK_F32X2(out, lo, hi) \
    asm("mov.b64 %0, {%1, %2};" : "=l"(out) : "f"(lo), "f"(hi))
#define UNPACK_F32X2(lo, hi, in) \
    asm("mov.b64 {%0, %1}, %2;" : "=f"(lo), "=f"(hi) : "l"(in))

// ---------------------------------------------------------------------------
// Fused transpose: q [SEQ][D] -> g_qT [D][SEQ] and emb [V][D] -> g_eT [D][V]
// ---------------------------------------------------------------------------
__global__ void transpose_kernel(const float* __restrict__ q,
                                 const float* __restrict__ emb) {
    __shared__ float tile[32][33];
    const float* in;
    float* out;
    int R, C, r0;
    if (blockIdx.y < SEQ_ / 32) {
        in = q;  out = g_qT;  R = SEQ_;  C = D_;  r0 = blockIdx.y * 32;
    } else {
        in = emb; out = g_eT; R = V_;    C = D_;  r0 = (blockIdx.y - SEQ_ / 32) * 32;
    }
    const float* inb = in + (size_t)blockIdx.z * R * C;
    float* outb = out + (size_t)blockIdx.z * R * C;
    int c0 = blockIdx.x * 32;
#pragma unroll
    for (int dy = 0; dy < 32; dy += 8)
        tile[threadIdx.y + dy][threadIdx.x] =
            inb[(size_t)(r0 + threadIdx.y + dy) * C + c0 + threadIdx.x];
    __syncthreads();
#pragma unroll
    for (int dy = 0; dy < 32; dy += 8)
        outb[(size_t)(c0 + threadIdx.y + dy) * R + r0 + threadIdx.x] =
            tile[threadIdx.x][threadIdx.y + dy];
}

// ---------------------------------------------------------------------------
// COMBINED kernel: GEMM producer CTAs + gather consumer CTAs, interleaved by
// m-tile so each m-tile's scores are produced just before its gathers run.
// GEMM CTA: 128(m) x 64(v) tile, 512 threads, 4x4 micro-tile via f32x2.
// Gather CTA: run-aligned chunk (<=32 panels), spins on g_ready[b][mt]==8.
// Per-mt CTA layout: 32 GEMM (4b x 8vt) then 16*(g+1) gather chunks, g=mt>>3.
// ---------------------------------------------------------------------------
__global__ __launch_bounds__(512, 3) void combined_kernel(
    const int* __restrict__ info,
    const int* __restrict__ idxs_batch,
    const int* __restrict__ idxs_row,
    float* __restrict__ out) {
    extern __shared__ float s[];   // 64 KB

    const int x = blockIdx.x;
    int mt, r;
    if (x < 384)       { mt = x / 48;                         r = x - mt * 48; }
    else if (x < 896)  { int y = x - 384;  mt = 8  + (y >> 6); r = y & 63; }
    else if (x < 1536) { int y = x - 896;  int d = y / 80; mt = 16 + d; r = y - d * 80; }
    else               { int y = x - 1536; int d = y / 96; mt = 24 + d; r = y - d * 96; }
    const int g = mt >> 3;
    const int tid = threadIdx.x;

    if (r < 32) {
        // ---------------- GEMM producer ----------------
        const int b = r & 3;
        const int vt = r >> 2;
        const int mBase = mt * 128;
        const int vBase = vt * 64;
        float* qs = s;            // [32][128]
        float* es = s + 4096;     // [32][64]
        const float* __restrict__ qTb = g_qT + (size_t)b * D_ * SEQ_;
        const float* __restrict__ eTb = g_eT + (size_t)b * D_ * V_;
        const int tx = tid & 15;   // v (16 x 4 = 64)
        const int ty = tid >> 4;   // m (32 x 4 = 128)

        u64 acc2[4][2];
#pragma unroll
        for (int i = 0; i < 4; ++i) { acc2[i][0] = 0ull; acc2[i][1] = 0ull; }

#pragma unroll
        for (int kp = 0; kp < 2; ++kp) {
            {
                int k = tid >> 5, f = tid & 31;
                *(float4*)&qs[k * 128 + f * 4] =
                    *(const float4*)&qTb[(size_t)(kp * 32 + k) * SEQ_ + mBase + f * 4];
                int u = tid + 512;
                int k1 = u >> 5, f1 = u & 31;
                *(float4*)&qs[k1 * 128 + f1 * 4] =
                    *(const float4*)&qTb[(size_t)(kp * 32 + k1) * SEQ_ + mBase + f1 * 4];
                int k2 = tid >> 4, f2 = tid & 15;
                *(float4*)&es[k2 * 64 + f2 * 4] =
                    *(const float4*)&eTb[(size_t)(kp * 32 + k2) * V_ + vBase + f2 * 4];
            }
            __syncthreads();
#pragma unroll 8
            for (int k = 0; k < 32; ++k) {
                float4 qv = *(const float4*)&qs[k * 128 + ty * 4];
                float4 ev = *(const float4*)&es[k * 64 + tx * 4];
                u64 ed0, ed1;
                PACK_F32X2(ed0, ev.x, ev.y);
                PACK_F32X2(ed1, ev.z, ev.w);
                float qa[4] = {qv.x, qv.y, qv.z, qv.w};
#pragma unroll
                for (int i = 0; i < 4; ++i) {
                    u64 qd;
                    PACK_F32X2(qd, qa[i], qa[i]);
                    FMA_F32X2(acc2[i][0], qd, ed0, acc2[i][0]);
                    FMA_F32X2(acc2[i][1], qd, ed1, acc2[i][1]);
                }
            }
            __syncthreads();
        }

#pragma unroll
        for (int i = 0; i < 4; ++i) {
            float o0, o1, o2, o3;
            UNPACK_F32X2(o0, o1, acc2[i][0]);
            UNPACK_F32X2(o2, o3, acc2[i][1]);
            float* dst = g_scores + ((size_t)b * SEQ_ + mBase + ty * 4 + i) * V_
                         + vBase + tx * 4;
            *(float4*)dst = make_float4(o0, o1, o2, o3);
        }
        __threadfence();
        __syncthreads();
        if (tid == 0) atomicAdd(&g_ready[b][mt], 1);
    } else {
        // ---------------- gather consumer ----------------
        const int j  = r - 32;
        const int bi = j & 3;
        const int jj = j >> 2;
        const int qd = jj / (g + 1);
        const int c  = jj - qd * (g + 1);
        const int rb_idx  = 4 * mt + qd;
        const int p_start = bi * PPB_ + (rb_idx * (rb_idx + 1)) / 2 + c * CHUNK;
        const int count   = min(CHUNK, rb_idx + 1 - c * CHUNK);

        const int b  = __ldg(&idxs_batch[p_start]);
        const int rb = __ldg(&idxs_row[p_start]);

        const int sub = tid >> 8;      // 0..1: which of 2 panels per iter
        const int t   = tid & 255;     // position within panel (4 elems)
        const float* srow = s + (t >> 3) * V_;

        // Prefetch first index vectors while waiting / staging
        int4 idx;
        if (sub < count)
            idx = ((const int4*)info)[(size_t)(p_start + sub) * 256 + t];

        // Wait for all 8 v-tiles of this m-tile
        if (tid == 0) {
            volatile int* fl = &g_ready[b][mt];
            while (*fl != 8) __nanosleep(128);
            __threadfence();
        }
        __syncthreads();

        // Stage the 32 score rows (64 KB), bypassing L1 for coherence
        {
            const float4* __restrict__ src = (const float4*)(
                g_scores + ((size_t)b * SEQ_ + rb * BS_) * V_);
            float4* dst = (float4*)s;
#pragma unroll
            for (int i = 0; i < 8; ++i)
                dst[tid + i * 512] = __ldcg(&src[tid + i * 512]);
        }
        __syncthreads();

        for (int pp = 0; pp < count; pp += 2) {
            const int pcur = pp + sub;
            int4 idxn;
            if (pcur + 2 < count)
                idxn = ((const int4*)info)[(size_t)(p_start + pcur + 2) * 256 + t];
            if (pcur < count) {
                float4 o;
                o.x = srow[idx.x];
                o.y = srow[idx.y];
                o.z = srow[idx.z];
                o.w = srow[idx.w];
                ((float4*)out)[(size_t)(p_start + pcur) * 256 + t] = o;
            }
            idx = idxn;
        }
    }
}

// ---------------------------------------------------------------------------
// Fallback path (any P / structure): serial GEMM + generic gather.
// ---------------------------------------------------------------------------
__global__ __launch_bounds__(256) void gemm_fallback_kernel() {
    __shared__ float qs[32][128];
    __shared__ float es[32][128];
    const int b = blockIdx.z;
    const int mBase = blockIdx.x * 128;
    const int vBase = blockIdx.y * 128;
    const int tid = threadIdx.x;
    const int tx = tid & 15;
    const int ty = tid >> 4;
    const float* __restrict__ qTb = g_qT + (size_t)b * D_ * SEQ_;
    const float* __restrict__ eTb = g_eT + (size_t)b * D_ * V_;
    float acc[8][8];
#pragma unroll
    for (int i = 0; i < 8; ++i)
#pragma unroll
        for (int j = 0; j < 8; ++j) acc[i][j] = 0.0f;
    const int f  = tid & 31;
    const int kr = tid >> 5;
#pragma unroll
    for (int kp = 0; kp < 2; ++kp) {
#pragma unroll
        for (int t = 0; t < 4; ++t) {
            int k = kr + t * 8;
            *(float4*)&qs[k][f * 4] =
                *(const float4*)&qTb[(size_t)(kp * 32 + k) * SEQ_ + mBase + f * 4];
            *(float4*)&es[k][f * 4] =
                *(const float4*)&eTb[(size_t)(kp * 32 + k) * V_ + vBase + f * 4];
        }
        __syncthreads();
#pragma unroll 8
        for (int k = 0; k < 32; ++k) {
            float qv[8], ev[8];
            *(float4*)&qv[0] = *(const float4*)&qs[k][ty * 8];
            *(float4*)&qv[4] = *(const float4*)&qs[k][ty * 8 + 4];
            *(float4*)&ev[0] = *(const float4*)&es[k][tx * 8];
            *(float4*)&ev[4] = *(const float4*)&es[k][tx * 8 + 4];
#pragma unroll
            for (int i = 0; i < 8; ++i)
#pragma unroll
                for (int j = 0; j < 8; ++j)
                    acc[i][j] = fmaf(qv[i], ev[j], acc[i][j]);
        }
        __syncthreads();
    }
#pragma unroll
    for (int i = 0; i < 8; ++i) {
        float* dst = g_scores + ((size_t)b * SEQ_ + mBase + ty * 8 + i) * V_
                     + vBase + tx * 8;
        *(float4*)dst = make_float4(acc[i][0], acc[i][1], acc[i][2], acc[i][3]);
        *(float4*)(dst + 4) = make_float4(acc[i][4], acc[i][5], acc[i][6], acc[i][7]);
    }
}

__global__ __launch_bounds__(256) void gather_fallback_kernel(
    const int* __restrict__ info,
    const int* __restrict__ idxs_batch,
    const int* __restrict__ idxs_row,
    float* __restrict__ out,
    int P) {
    extern __shared__ float s[];
    const int p0 = blockIdx.x * 16;
    if (p0 >= P) return;
    const int pend = min(p0 + 16, P);
    const int tid = threadIdx.x;
    const float* srow = s + (tid >> 3) * V_;
    int cached = -1;
    int4 idx = ((const int4*)(info + (size_t)p0 * 1024))[tid];
    for (int p = p0; p < pend; ++p) {
        int4 idx_next;
        if (p + 1 < pend)
            idx_next = ((const int4*)(info + (size_t)(p + 1) * 1024))[tid];
        const int b  = __ldg(&idxs_batch[p]);
        const int rb = __ldg(&idxs_row[p]);
        const int key = (b << 16) | rb;
        if (key != cached) {
            __syncthreads();
            const float4* __restrict__ src = (const float4*)(
                g_scores + ((size_t)b * SEQ_ + rb * BS_) * V_);
            float4* dst = (float4*)s;
#pragma unroll
            for (int t2 = 0; t2 < 16; ++t2)
                dst[tid + t2 * 256] = src[tid + t2 * 256];
            cached = key;
            __syncthreads();
        }
        float4 o;
        o.x = srow[idx.x];
        o.y = srow[idx.y];
        o.z = srow[idx.z];
        o.w = srow[idx.w];
        ((float4*)(out + (size_t)p * 1024))[tid] = o;
        idx = idx_next;
    }
}

// ---------------------------------------------------------------------------
extern "C" void kernel_launch(void* const* d_in, const int* in_sizes, int n_in,
                              void* d_out, int out_size) {
    const float* q    = (const float*)d_in[0];
    const float* emb  = (const float*)d_in[1];
    const int*   info = (const int*)d_in[2];
    const int*   idxb = (const int*)d_in[3];
    const int*   idxr = (const int*)d_in[4];
    float* out = (float*)d_out;
    const int P = in_sizes[3];

    static int init_done = 0;
    if (!init_done) {
        cudaFuncSetAttribute(combined_kernel,
                             cudaFuncAttributeMaxDynamicSharedMemorySize,
                             BS_ * V_ * sizeof(float));
        cudaFuncSetAttribute(gather_fallback_kernel,
                             cudaFuncAttributeMaxDynamicSharedMemorySize,
                             BS_ * V_ * sizeof(float));
        init_done = 1;
    }

    void* ready_ptr = nullptr;
    cudaGetSymbolAddress(&ready_ptr, g_ready);
    cudaMemsetAsync(ready_ptr, 0, sizeof(int) * B_ * 32, 0);

    dim3 tb(32, 8);
    transpose_kernel<<<dim3(D_ / 32, SEQ_ / 32 + V_ / 32, B_), tb>>>(q, emb);

    if (P == B_ * PPB_) {
        combined_kernel<<<2304, 512, BS_ * V_ * sizeof(float)>>>(
            info, idxb, idxr, out);
    } else {
        gemm_fallback_kernel<<<dim3(SEQ_ / 128, V_ / 128, B_), 256>>>();
        gather_fallback_kernel<<<(P + 15) / 16, 256, BS_ * V_ * sizeof(float)>>>(
            info, idxb, idxr, out, P);
    }
}

// round 6
// speedup vs baseline: 1.4264x; 1.4264x over previous
#include <cuda_runtime.h>
#include <cuda_bf16.h>

#define B_    4
#define SEQ_  4096
#define D_    64
#define V_    512
#define BS_   32
#define R_    128          // SEQ/BS
#define PPB_  8256         // panels per batch = R(R+1)/2
#define CHUNK 32           // max panels per gather CTA (run-aligned)
#define PAD   72           // bf16 row pitch (144B): (4g+t) banks, conflict-free

// Scratch (device globals — no allocation allowed)
__device__ float g_scores[(size_t)B_ * SEQ_ * V_];        // [b][m][v]

#define MMA_BF16(c, a, b)                                                     \
    asm volatile(                                                             \
        "mma.sync.aligned.m16n8k16.row.col.f32.bf16.bf16.f32 "               \
        "{%0,%1,%2,%3}, {%4,%5,%6,%7}, {%8,%9}, {%0,%1,%2,%3};"              \
        : "+f"((c)[0]), "+f"((c)[1]), "+f"((c)[2]), "+f"((c)[3])              \
        : "r"((a)[0]), "r"((a)[1]), "r"((a)[2]), "r"((a)[3]),                 \
          "r"((b)[0]), "r"((b)[1]))

// ---------------------------------------------------------------------------
// GEMM via bf16-split tensor cores: scores = q @ emb^T (fp32-accurate).
// x = hi + lo (both bf16); x*y ~= hi*hi + hi*lo + lo*hi  (lo*lo dropped).
// CTA: 256 threads (8 warps), tile 128(m) x 128(v), full K=64.
// Warp tile 32(m) x 64(v): 2x8 m16n8 tiles, 4 k16 steps, 3 mma per product.
// No input transposes needed: A = q[m][k] row-major, B = emb[v][k] (col-major
// k x n from mma's perspective).
// ---------------------------------------------------------------------------
__global__ __launch_bounds__(256) void gemm_mma_kernel(
    const float* __restrict__ q, const float* __restrict__ emb) {
    extern __shared__ __nv_bfloat16 sm[];
    __nv_bfloat16* a_hi = sm;                    // [128][PAD]
    __nv_bfloat16* a_lo = a_hi + 128 * PAD;
    __nv_bfloat16* b_hi = a_lo + 128 * PAD;
    __nv_bfloat16* b_lo = b_hi + 128 * PAD;

    const int b = blockIdx.z;
    const int mBase = blockIdx.x * 128;
    const int vBase = blockIdx.y * 128;
    const int tid = threadIdx.x;

    // ---- Load + split: 128x64 fp32 -> hi/lo bf16 planes (q and emb) ----
    const float* __restrict__ qb = q + ((size_t)b * SEQ_ + mBase) * D_;
    const float* __restrict__ eb = emb + ((size_t)b * V_ + vBase) * D_;
#pragma unroll
    for (int i = 0; i < 8; ++i) {
        int lin = tid + i * 256;          // 0..2047
        int row = lin >> 4;
        int c4 = (lin & 15) * 4;
        float4 xq = *(const float4*)&qb[row * D_ + c4];
        float4 xe = *(const float4*)&eb[row * D_ + c4];

        float aq[4] = {xq.x, xq.y, xq.z, xq.w};
        float ae[4] = {xe.x, xe.y, xe.z, xe.w};
        __nv_bfloat16 qh[4], ql[4], eh[4], el[4];
#pragma unroll
        for (int u = 0; u < 4; ++u) {
            qh[u] = __float2bfloat16(aq[u]);
            ql[u] = __float2bfloat16(aq[u] - __bfloat162float(qh[u]));
            eh[u] = __float2bfloat16(ae[u]);
            el[u] = __float2bfloat16(ae[u] - __bfloat162float(eh[u]));
        }
        int o = row * PAD + c4;
        *(__nv_bfloat162*)&a_hi[o]     = __halves2bfloat162(qh[0], qh[1]);
        *(__nv_bfloat162*)&a_hi[o + 2] = __halves2bfloat162(qh[2], qh[3]);
        *(__nv_bfloat162*)&a_lo[o]     = __halves2bfloat162(ql[0], ql[1]);
        *(__nv_bfloat162*)&a_lo[o + 2] = __halves2bfloat162(ql[2], ql[3]);
        *(__nv_bfloat162*)&b_hi[o]     = __halves2bfloat162(eh[0], eh[1]);
        *(__nv_bfloat162*)&b_hi[o + 2] = __halves2bfloat162(eh[2], eh[3]);
        *(__nv_bfloat162*)&b_lo[o]     = __halves2bfloat162(el[0], el[1]);
        *(__nv_bfloat162*)&b_lo[o + 2] = __halves2bfloat162(el[2], el[3]);
    }
    __syncthreads();

    // ---- MMA ----
    const int wid = tid >> 5, lane = tid & 31;
    const int wm = wid & 3;      // warp m position (4 x 32 = 128)
    const int wv = wid >> 2;     // warp v position (2 x 64 = 128)
    const int g = lane >> 2;     // group id (row within fragment)
    const int t4 = lane & 3;     // thread-in-group (col pairs)

    float c[2][8][4];
#pragma unroll
    for (int mi = 0; mi < 2; ++mi)
#pragma unroll
        for (int ni = 0; ni < 8; ++ni)
#pragma unroll
            for (int u = 0; u < 4; ++u) c[mi][ni][u] = 0.0f;

#pragma unroll
    for (int ks = 0; ks < 4; ++ks) {
        const int k0 = ks * 16 + 2 * t4;
        unsigned ahi[2][4], alo[2][4];
#pragma unroll
        for (int mi = 0; mi < 2; ++mi) {
            int r0 = wm * 32 + mi * 16 + g;
            ahi[mi][0] = *(unsigned*)&a_hi[r0 * PAD + k0];
            ahi[mi][1] = *(unsigned*)&a_hi[(r0 + 8) * PAD + k0];
            ahi[mi][2] = *(unsigned*)&a_hi[r0 * PAD + k0 + 8];
            ahi[mi][3] = *(unsigned*)&a_hi[(r0 + 8) * PAD + k0 + 8];
            alo[mi][0] = *(unsigned*)&a_lo[r0 * PAD + k0];
            alo[mi][1] = *(unsigned*)&a_lo[(r0 + 8) * PAD + k0];
            alo[mi][2] = *(unsigned*)&a_lo[r0 * PAD + k0 + 8];
            alo[mi][3] = *(unsigned*)&a_lo[(r0 + 8) * PAD + k0 + 8];
        }
#pragma unroll
        for (int ni = 0; ni < 8; ++ni) {
            int n0 = wv * 64 + ni * 8 + g;
            unsigned bhi[2], blo[2];
            bhi[0] = *(unsigned*)&b_hi[n0 * PAD + k0];
            bhi[1] = *(unsigned*)&b_hi[n0 * PAD + k0 + 8];
            blo[0] = *(unsigned*)&b_lo[n0 * PAD + k0];
            blo[1] = *(unsigned*)&b_lo[n0 * PAD + k0 + 8];
#pragma unroll
            for (int mi = 0; mi < 2; ++mi) {
                MMA_BF16(c[mi][ni], ahi[mi], bhi);
                MMA_BF16(c[mi][ni], ahi[mi], blo);
                MMA_BF16(c[mi][ni], alo[mi], bhi);
            }
        }
    }

    // ---- Epilogue: fp32 scores ----
#pragma unroll
    for (int mi = 0; mi < 2; ++mi) {
#pragma unroll
        for (int ni = 0; ni < 8; ++ni) {
            int r0 = mBase + wm * 32 + mi * 16 + g;
            int col = vBase + wv * 64 + ni * 8 + 2 * t4;
            float* dst = g_scores + ((size_t)b * SEQ_ + r0) * V_ + col;
            *(float2*)dst = make_float2(c[mi][ni][0], c[mi][ni][1]);
            *(float2*)(dst + 8 * V_) = make_float2(c[mi][ni][2], c[mi][ni][3]);
        }
    }
}

// ---------------------------------------------------------------------------
// Run-aligned gather (round-4 best). For batch b, row-block rb there are rb+1
// consecutive panels; each CTA owns <=32 panels of ONE run, staging the 32
// score rows (64 KB) exactly once. 1024 threads: 4 panels/iter, 4 elems/thr.
// ---------------------------------------------------------------------------
__global__ __launch_bounds__(1024) void gather_run_kernel(
    const int* __restrict__ info,
    const int* __restrict__ idxs_batch,
    const int* __restrict__ idxs_row,
    float* __restrict__ out) {
    extern __shared__ float s[];   // 64 KB: 32 rows x 512 floats

    const int x  = blockIdx.x;
    const int bi = x / 320;
    const int xb = x - bi * 320;
    int g, base;
    if (xb < 32)       { g = 0; base = 0;   }
    else if (xb < 96)  { g = 1; base = 32;  }
    else if (xb < 192) { g = 2; base = 96;  }
    else               { g = 3; base = 192; }
    const int rb_idx = (g << 5) + (xb - base) / (g + 1);
    const int c      = (xb - base) % (g + 1);
    const int p_start = bi * PPB_ + (rb_idx * (rb_idx + 1)) / 2 + c * CHUNK;
    const int count   = min(CHUNK, rb_idx + 1 - c * CHUNK);

    const int b  = __ldg(&idxs_batch[p_start]);
    const int rb = __ldg(&idxs_row[p_start]);

    const int tid = threadIdx.x;
    const int sub = tid >> 8;      // which of 4 panels this iteration (0..3)
    const int t   = tid & 255;     // position within panel (4 elems)
    const float* srow = s + (t >> 3) * V_;

    int4 idx;
    if (sub < count)
        idx = ((const int4*)info)[(size_t)(p_start + sub) * 256 + t];

    {
        const float4* __restrict__ src = (const float4*)(
            g_scores + ((size_t)b * SEQ_ + rb * BS_) * V_);
        float4* dst = (float4*)s;
#pragma unroll
        for (int i = 0; i < 4; ++i)
            dst[tid + i * 1024] = src[tid + i * 1024];
    }
    __syncthreads();

    for (int pp = 0; pp < count; pp += 4) {
        const int pcur = pp + sub;
        const int pnext = pcur + 4;
        int4 idxn;
        if (pnext < count)
            idxn = ((const int4*)info)[(size_t)(p_start + pnext) * 256 + t];

        if (pcur < count) {
            float4 o;
            o.x = srow[idx.x];
            o.y = srow[idx.y];
            o.z = srow[idx.z];
            o.w = srow[idx.w];
            ((float4*)out)[(size_t)(p_start + pcur) * 256 + t] = o;
        }
        idx = idxn;
    }
}

// ---------------------------------------------------------------------------
// Generic fallback gather (any P / structure).
// ---------------------------------------------------------------------------
__global__ __launch_bounds__(256) void gather_fallback_kernel(
    const int* __restrict__ info,
    const int* __restrict__ idxs_batch,
    const int* __restrict__ idxs_row,
    float* __restrict__ out,
    int P) {
    extern __shared__ float s[];
    const int p0 = blockIdx.x * 16;
    if (p0 >= P) return;
    const int pend = min(p0 + 16, P);
    const int tid = threadIdx.x;
    const float* srow = s + (tid >> 3) * V_;

    int cached = -1;
    int4 idx = ((const int4*)(info + (size_t)p0 * 1024))[tid];
    for (int p = p0; p < pend; ++p) {
        int4 idx_next;
        if (p + 1 < pend)
            idx_next = ((const int4*)(info + (size_t)(p + 1) * 1024))[tid];
        const int b  = __ldg(&idxs_batch[p]);
        const int rb = __ldg(&idxs_row[p]);
        const int key = (b << 16) | rb;
        if (key != cached) {
            __syncthreads();
            const float4* __restrict__ src = (const float4*)(
                g_scores + ((size_t)b * SEQ_ + rb * BS_) * V_);
            float4* dst = (float4*)s;
#pragma unroll
            for (int t2 = 0; t2 < 16; ++t2)
                dst[tid + t2 * 256] = src[tid + t2 * 256];
            cached = key;
            __syncthreads();
        }
        float4 o;
        o.x = srow[idx.x];
        o.y = srow[idx.y];
        o.z = srow[idx.z];
        o.w = srow[idx.w];
        ((float4*)(out + (size_t)p * 1024))[tid] = o;
        idx = idx_next;
    }
}

// ---------------------------------------------------------------------------
extern "C" void kernel_launch(void* const* d_in, const int* in_sizes, int n_in,
                              void* d_out, int out_size) {
    const float* q    = (const float*)d_in[0];
    const float* emb  = (const float*)d_in[1];
    const int*   info = (const int*)d_in[2];
    const int*   idxb = (const int*)d_in[3];
    const int*   idxr = (const int*)d_in[4];
    float* out = (float*)d_out;
    const int P = in_sizes[3];

    const int gemm_smem = 4 * 128 * PAD * (int)sizeof(__nv_bfloat16);  // 72 KB

    static int init_done = 0;
    if (!init_done) {
        cudaFuncSetAttribute(gemm_mma_kernel,
                             cudaFuncAttributeMaxDynamicSharedMemorySize,
                             gemm_smem);
        cudaFuncSetAttribute(gather_run_kernel,
                             cudaFuncAttributeMaxDynamicSharedMemorySize,
                             BS_ * V_ * sizeof(float));
        cudaFuncSetAttribute(gather_fallback_kernel,
                             cudaFuncAttributeMaxDynamicSharedMemorySize,
                             BS_ * V_ * sizeof(float));
        init_done = 1;
    }

    gemm_mma_kernel<<<dim3(SEQ_ / 128, V_ / 128, B_), 256, gemm_smem>>>(q, emb);

    if (P == B_ * PPB_) {
        gather_run_kernel<<<B_ * 320, 1024, BS_ * V_ * sizeof(float)>>>(
            info, idxb, idxr, out);
    } else {
        gather_fallback_kernel<<<(P + 15) / 16, 256, BS_ * V_ * sizeof(float)>>>(
            info, idxb, idxr, out, P);
    }
}

// round 7
// speedup vs baseline: 1.4844x; 1.0407x over previous
#include <cuda_runtime.h>
#include <cuda_bf16.h>

#define B_    4
#define SEQ_  4096
#define D_    64
#define V_    512
#define BS_   32
#define R_    128          // SEQ/BS
#define PPB_  8256         // panels per batch = R(R+1)/2
#define CHUNK 32           // max panels per gather CTA (run-aligned)
#define PAD   72           // bf16 row pitch (144B): (4g+t) banks, conflict-free

// Scratch (device globals — no allocation allowed)
__device__ float g_scores[(size_t)B_ * SEQ_ * V_];              // [b][m][v]
__device__ __nv_bfloat16 g_qhi[(size_t)B_ * SEQ_ * D_];
__device__ __nv_bfloat16 g_qlo[(size_t)B_ * SEQ_ * D_];
__device__ __nv_bfloat16 g_ehi[(size_t)B_ * V_ * D_];
__device__ __nv_bfloat16 g_elo[(size_t)B_ * V_ * D_];

#define MMA_BF16(c, a, b)                                                     \
    asm volatile(                                                             \
        "mma.sync.aligned.m16n8k16.row.col.f32.bf16.bf16.f32 "               \
        "{%0,%1,%2,%3}, {%4,%5,%6,%7}, {%8,%9}, {%0,%1,%2,%3};"              \
        : "+f"((c)[0]), "+f"((c)[1]), "+f"((c)[2]), "+f"((c)[3])              \
        : "r"((a)[0]), "r"((a)[1]), "r"((a)[2]), "r"((a)[3]),                 \
          "r"((b)[0]), "r"((b)[1]))

// ---------------------------------------------------------------------------
// One-time split: fp32 -> (hi, lo) bf16 planes for q and emb.
// x = hi + lo exactly captures 16 mantissa bits; hi*hi + hi*lo + lo*hi keeps
// the product accurate to ~2^-17 relative.
// ---------------------------------------------------------------------------
__global__ __launch_bounds__(256) void split_kernel(
    const float* __restrict__ q, const float* __restrict__ emb) {
    const int NQ4 = B_ * SEQ_ * D_ / 4;   // 262144
    const int NE4 = B_ * V_ * D_ / 4;     // 32768
    int i = blockIdx.x * 256 + threadIdx.x;
    const float* src;
    __nv_bfloat16 *hi, *lo;
    int j;
    if (i < NQ4)            { src = q;   hi = g_qhi; lo = g_qlo; j = i; }
    else if (i < NQ4 + NE4) { src = emb; hi = g_ehi; lo = g_elo; j = i - NQ4; }
    else return;

    float4 x = ((const float4*)src)[j];
    float a[4] = {x.x, x.y, x.z, x.w};
    __nv_bfloat16 h[4], l[4];
#pragma unroll
    for (int u = 0; u < 4; ++u) {
        h[u] = __float2bfloat16(a[u]);
        l[u] = __float2bfloat16(a[u] - __bfloat162float(h[u]));
    }
    *(__nv_bfloat162*)&hi[j * 4]     = __halves2bfloat162(h[0], h[1]);
    *(__nv_bfloat162*)&hi[j * 4 + 2] = __halves2bfloat162(h[2], h[3]);
    *(__nv_bfloat162*)&lo[j * 4]     = __halves2bfloat162(l[0], l[1]);
    *(__nv_bfloat162*)&lo[j * 4 + 2] = __halves2bfloat162(l[2], l[3]);
}

// ---------------------------------------------------------------------------
// GEMM via bf16-split tensor cores: scores = q @ emb^T (fp32-accurate).
// CTA: 256 threads (8 warps), tile 128(m) x 128(v), full K=64.
// Prologue is now pure uint4 copies of the pre-split planes.
// ---------------------------------------------------------------------------
__global__ __launch_bounds__(256) void gemm_mma_kernel() {
    extern __shared__ __nv_bfloat16 sm[];
    __nv_bfloat16* a_hi = sm;                    // [128][PAD]
    __nv_bfloat16* a_lo = a_hi + 128 * PAD;
    __nv_bfloat16* b_hi = a_lo + 128 * PAD;
    __nv_bfloat16* b_lo = b_hi + 128 * PAD;

    const int b = blockIdx.z;
    const int mBase = blockIdx.x * 128;
    const int vBase = blockIdx.y * 128;
    const int tid = threadIdx.x;

    // ---- Copy pre-split planes into padded smem (coalesced uint4) ----
    {
        const uint4* __restrict__ srcs[4] = {
            (const uint4*)(g_qhi + ((size_t)b * SEQ_ + mBase) * D_),
            (const uint4*)(g_qlo + ((size_t)b * SEQ_ + mBase) * D_),
            (const uint4*)(g_ehi + ((size_t)b * V_ + vBase) * D_),
            (const uint4*)(g_elo + ((size_t)b * V_ + vBase) * D_)};
        __nv_bfloat16* dsts[4] = {a_hi, a_lo, b_hi, b_lo};
#pragma unroll
        for (int it = 0; it < 16; ++it) {
            int lin = tid + it * 256;        // 0..4095
            int plane = lin >> 10;           // 1024 uint4 per plane
            int r = (lin >> 3) & 127;        // row
            int ch = lin & 7;                // 8-bf16 chunk
            *(uint4*)&dsts[plane][r * PAD + ch * 8] = srcs[plane][r * 8 + ch];
        }
    }
    __syncthreads();

    // ---- MMA (validated round-6 core) ----
    const int wid = tid >> 5, lane = tid & 31;
    const int wm = wid & 3;      // warp m position (4 x 32 = 128)
    const int wv = wid >> 2;     // warp v position (2 x 64 = 128)
    const int g = lane >> 2;     // group id (row within fragment)
    const int t4 = lane & 3;     // thread-in-group (col pairs)

    float c[2][8][4];
#pragma unroll
    for (int mi = 0; mi < 2; ++mi)
#pragma unroll
        for (int ni = 0; ni < 8; ++ni)
#pragma unroll
            for (int u = 0; u < 4; ++u) c[mi][ni][u] = 0.0f;

#pragma unroll
    for (int ks = 0; ks < 4; ++ks) {
        const int k0 = ks * 16 + 2 * t4;
        unsigned ahi[2][4], alo[2][4];
#pragma unroll
        for (int mi = 0; mi < 2; ++mi) {
            int r0 = wm * 32 + mi * 16 + g;
            ahi[mi][0] = *(unsigned*)&a_hi[r0 * PAD + k0];
            ahi[mi][1] = *(unsigned*)&a_hi[(r0 + 8) * PAD + k0];
            ahi[mi][2] = *(unsigned*)&a_hi[r0 * PAD + k0 + 8];
            ahi[mi][3] = *(unsigned*)&a_hi[(r0 + 8) * PAD + k0 + 8];
            alo[mi][0] = *(unsigned*)&a_lo[r0 * PAD + k0];
            alo[mi][1] = *(unsigned*)&a_lo[(r0 + 8) * PAD + k0];
            alo[mi][2] = *(unsigned*)&a_lo[r0 * PAD + k0 + 8];
            alo[mi][3] = *(unsigned*)&a_lo[(r0 + 8) * PAD + k0 + 8];
        }
#pragma unroll
        for (int ni = 0; ni < 8; ++ni) {
            int n0 = wv * 64 + ni * 8 + g;
            unsigned bhi[2], blo[2];
            bhi[0] = *(unsigned*)&b_hi[n0 * PAD + k0];
            bhi[1] = *(unsigned*)&b_hi[n0 * PAD + k0 + 8];
            blo[0] = *(unsigned*)&b_lo[n0 * PAD + k0];
            blo[1] = *(unsigned*)&b_lo[n0 * PAD + k0 + 8];
#pragma unroll
            for (int mi = 0; mi < 2; ++mi) {
                MMA_BF16(c[mi][ni], ahi[mi], bhi);
                MMA_BF16(c[mi][ni], ahi[mi], blo);
                MMA_BF16(c[mi][ni], alo[mi], bhi);
            }
        }
    }

    // ---- Epilogue: fp32 scores ----
#pragma unroll
    for (int mi = 0; mi < 2; ++mi) {
#pragma unroll
        for (int ni = 0; ni < 8; ++ni) {
            int r0 = mBase + wm * 32 + mi * 16 + g;
            int col = vBase + wv * 64 + ni * 8 + 2 * t4;
            float* dst = g_scores + ((size_t)b * SEQ_ + r0) * V_ + col;
            *(float2*)dst = make_float2(c[mi][ni][0], c[mi][ni][1]);
            *(float2*)(dst + 8 * V_) = make_float2(c[mi][ni][2], c[mi][ni][3]);
        }
    }
}

// ---------------------------------------------------------------------------
// Run-aligned gather. For batch b, row-block rb there are rb+1 consecutive
// panels; each CTA owns <=32 panels of ONE run, staging the 32 score rows
// (64 KB) exactly once. 1024 threads: 4 panels/iter, 4 elems/thread.
// Streaming hints: info read-once (ldcs), out write-once (stcs) keep L2 free
// for the scores staging reads.
// ---------------------------------------------------------------------------
__global__ __launch_bounds__(1024) void gather_run_kernel(
    const int* __restrict__ info,
    const int* __restrict__ idxs_batch,
    const int* __restrict__ idxs_row,
    float* __restrict__ out) {
    extern __shared__ float s[];   // 64 KB: 32 rows x 512 floats

    const int x  = blockIdx.x;
    const int bi = x / 320;
    const int xb = x - bi * 320;
    int g, base;
    if (xb < 32)       { g = 0; base = 0;   }
    else if (xb < 96)  { g = 1; base = 32;  }
    else if (xb < 192) { g = 2; base = 96;  }
    else               { g = 3; base = 192; }
    const int rb_idx = (g << 5) + (xb - base) / (g + 1);
    const int c      = (xb - base) % (g + 1);
    const int p_start = bi * PPB_ + (rb_idx * (rb_idx + 1)) / 2 + c * CHUNK;
    const int count   = min(CHUNK, rb_idx + 1 - c * CHUNK);

    const int b  = __ldg(&idxs_batch[p_start]);
    const int rb = __ldg(&idxs_row[p_start]);

    const int tid = threadIdx.x;
    const int sub = tid >> 8;      // which of 4 panels this iteration (0..3)
    const int t   = tid & 255;     // position within panel (4 elems)
    const float* srow = s + (t >> 3) * V_;

    int4 idx;
    if (sub < count)
        idx = __ldcs(&((const int4*)info)[(size_t)(p_start + sub) * 256 + t]);

    {
        const float4* __restrict__ src = (const float4*)(
            g_scores + ((size_t)b * SEQ_ + rb * BS_) * V_);
        float4* dst = (float4*)s;
#pragma unroll
        for (int i = 0; i < 4; ++i)
            dst[tid + i * 1024] = src[tid + i * 1024];
    }
    __syncthreads();

    for (int pp = 0; pp < count; pp += 4) {
        const int pcur = pp + sub;
        const int pnext = pcur + 4;
        int4 idxn;
        if (pnext < count)
            idxn = __ldcs(&((const int4*)info)[(size_t)(p_start + pnext) * 256 + t]);

        if (pcur < count) {
            float4 o;
            o.x = srow[idx.x];
            o.y = srow[idx.y];
            o.z = srow[idx.z];
            o.w = srow[idx.w];
            __stcs(&((float4*)out)[(size_t)(p_start + pcur) * 256 + t], o);
        }
        idx = idxn;
    }
}

// ---------------------------------------------------------------------------
// Generic fallback gather (any P / structure).
// ---------------------------------------------------------------------------
__global__ __launch_bounds__(256) void gather_fallback_kernel(
    const int* __restrict__ info,
    const int* __restrict__ idxs_batch,
    const int* __restrict__ idxs_row,
    float* __restrict__ out,
    int P) {
    extern __shared__ float s[];
    const int p0 = blockIdx.x * 16;
    if (p0 >= P) return;
    const int pend = min(p0 + 16, P);
    const int tid = threadIdx.x;
    const float* srow = s + (tid >> 3) * V_;

    int cached = -1;
    int4 idx = ((const int4*)(info + (size_t)p0 * 1024))[tid];
    for (int p = p0; p < pend; ++p) {
        int4 idx_next;
        if (p + 1 < pend)
            idx_next = ((const int4*)(info + (size_t)(p + 1) * 1024))[tid];
        const int b  = __ldg(&idxs_batch[p]);
        const int rb = __ldg(&idxs_row[p]);
        const int key = (b << 16) | rb;
        if (key != cached) {
            __syncthreads();
            const float4* __restrict__ src = (const float4*)(
                g_scores + ((size_t)b * SEQ_ + rb * BS_) * V_);
            float4* dst = (float4*)s;
#pragma unroll
            for (int t2 = 0; t2 < 16; ++t2)
                dst[tid + t2 * 256] = src[tid + t2 * 256];
            cached = key;
            __syncthreads();
        }
        float4 o;
        o.x = srow[idx.x];
        o.y = srow[idx.y];
        o.z = srow[idx.z];
        o.w = srow[idx.w];
        ((float4*)(out + (size_t)p * 1024))[tid] = o;
        idx = idx_next;
    }
}

// ---------------------------------------------------------------------------
extern "C" void kernel_launch(void* const* d_in, const int* in_sizes, int n_in,
                              void* d_out, int out_size) {
    const float* q    = (const float*)d_in[0];
    const float* emb  = (const float*)d_in[1];
    const int*   info = (const int*)d_in[2];
    const int*   idxb = (const int*)d_in[3];
    const int*   idxr = (const int*)d_in[4];
    float* out = (float*)d_out;
    const int P = in_sizes[3];

    const int gemm_smem = 4 * 128 * PAD * (int)sizeof(__nv_bfloat16);  // 72 KB

    static int init_done = 0;
    if (!init_done) {
        cudaFuncSetAttribute(gemm_mma_kernel,
                             cudaFuncAttributeMaxDynamicSharedMemorySize,
                             gemm_smem);
        cudaFuncSetAttribute(gather_run_kernel,
                             cudaFuncAttributeMaxDynamicSharedMemorySize,
                             BS_ * V_ * sizeof(float));
        cudaFuncSetAttribute(gather_fallback_kernel,
                             cudaFuncAttributeMaxDynamicSharedMemorySize,
                             BS_ * V_ * sizeof(float));
        init_done = 1;
    }

    const int NSPLIT = (B_ * SEQ_ * D_ + B_ * V_ * D_) / 4;  // float4 count
    split_kernel<<<(NSPLIT + 255) / 256, 256>>>(q, emb);

    gemm_mma_kernel<<<dim3(SEQ_ / 128, V_ / 128, B_), 256, gemm_smem>>>();

    if (P == B_ * PPB_) {
        gather_run_kernel<<<B_ * 320, 1024, BS_ * V_ * sizeof(float)>>>(
            info, idxb, idxr, out);
    } else {
        gather_fallback_kernel<<<(P + 15) / 16, 256, BS_ * V_ * sizeof(float)>>>(
            info, idxb, idxr, out, P);
    }
}